// round 15
// baseline (speedup 1.0000x reference)
#include <cuda_runtime.h>
#include <cuda_bf16.h>
#include <cuda_fp16.h>
#include <cstdint>
#include <cstddef>

// ---------------------------------------------------------------------------
// SageLayer pipeline v14: R8 structure (validated 124.5us best) with a
// 2-rows-per-warp norm kernel (interleaved loads -> 2x MLP on the
// latency-bound final pass). fold_gather and GEMM are R8-verbatim.
//   out[b] = normalize(leaky( X @ A^T + c ))[nodes_idx]
//   X[u] = [ emb[uid[u]] | mean_k emb[adj[u,k]] | mean_k emb[dis[u,k]] ]
//   Weights folded to one 384x384 fp16 matrix inside the gather launch.
// ---------------------------------------------------------------------------

#define U_NODES 16384
#define K_NEIGH 32
#define D_IN    128
#define D_OUT   384
#define B_OUT   32768
#define FOLD_BLOCKS 384

// ---- device scratch ----
__device__ __align__(16) float g_c[384];
__device__ __align__(16) __half g_X[(size_t)U_NODES * 384];
__device__ __align__(16) __half g_B[384 * 384];            // folded A[n][k]
__device__ __align__(16) float g_Y[(size_t)U_NODES * 384];

// ---- helpers ----
__device__ __forceinline__ uint32_t smem_u32(const void* p) {
    uint32_t a;
    asm("{ .reg .u64 t; cvta.to.shared.u64 t, %1; cvt.u32.u64 %0, t; }"
        : "=r"(a) : "l"(p));
    return a;
}
__device__ __forceinline__ void cp_async16(uint32_t dst, const void* src) {
    asm volatile("cp.async.cg.shared.global [%0], [%1], 16;"
                 :: "r"(dst), "l"(src) : "memory");
}
__device__ __forceinline__ void cp_commit() {
    asm volatile("cp.async.commit_group;" ::: "memory");
}
template <int N>
__device__ __forceinline__ void cp_wait() {
    asm volatile("cp.async.wait_group %0;" :: "n"(N) : "memory");
}
__device__ __forceinline__ void ldsm_x4(uint32_t& r0, uint32_t& r1,
                                        uint32_t& r2, uint32_t& r3, uint32_t a) {
    asm volatile("ldmatrix.sync.aligned.m8n8.x4.shared.b16 {%0,%1,%2,%3}, [%4];"
                 : "=r"(r0), "=r"(r1), "=r"(r2), "=r"(r3) : "r"(a));
}
__device__ __forceinline__ void mma16816(float& c0, float& c1, float& c2, float& c3,
                                         uint32_t a0, uint32_t a1, uint32_t a2, uint32_t a3,
                                         uint32_t b0, uint32_t b1) {
    asm volatile(
        "mma.sync.aligned.m16n8k16.row.col.f32.f16.f16.f32 "
        "{%0,%1,%2,%3}, {%4,%5,%6,%7}, {%8,%9}, {%0,%1,%2,%3};"
        : "+f"(c0), "+f"(c1), "+f"(c2), "+f"(c3)
        : "r"(a0), "r"(a1), "r"(a2), "r"(a3), "r"(b0), "r"(b1));
}
__device__ __forceinline__ uint32_t pack_half2_u32(float a, float b) {
    __half2 h = __floats2half2_rn(a, b);
    return *(uint32_t*)&h;
}

// ---------------------------------------------------------------------------
// fused fold + gather kernel (R8-validated, unchanged)
//   blocks [0, 384):        fold output-row n of B and c
//   blocks [384, 384+16384): gather+mean node u = blockIdx.x - 384
// ---------------------------------------------------------------------------
__global__ void __launch_bounds__(128) fold_gather_kernel(
        const float* __restrict__ emb,
        const int* __restrict__ uid,
        const int* __restrict__ adj,
        const int* __restrict__ dis,
        const float* __restrict__ Wa_adj,
        const float* __restrict__ ba_adj,
        const float* __restrict__ Wa_dis,
        const float* __restrict__ ba_dis,
        const float* __restrict__ W_self,
        const float* __restrict__ W_adj,
        const float* __restrict__ W_dis,
        const float* __restrict__ WC,
        const float* __restrict__ bWC,
        const float* __restrict__ bias) {
    const int t = threadIdx.x;

    if (blockIdx.x < FOLD_BLOCKS) {
        const int n = blockIdx.x;
        __shared__ float wcn[384];
        __shared__ float tbuf[128];
        __shared__ float red[128];

        wcn[t]       = WC[n * 384 + t];
        wcn[t + 128] = WC[n * 384 + 128 + t];
        wcn[t + 256] = WC[n * 384 + 256 + t];
        __syncthreads();

        {
            float a = 0.f;
#pragma unroll 8
            for (int e = 0; e < 128; e++)
                a += wcn[e] * W_self[e * 128 + t];
            g_B[n * 384 + t] = __float2half_rn(a);
        }

        float csum = 0.f;

        {
            float tv = 0.f;
#pragma unroll 8
            for (int g = 0; g < 128; g++)
                tv += wcn[128 + g] * W_adj[g * 128 + t];
            tbuf[t] = tv;
            __syncthreads();
            float a2 = 0.f;
#pragma unroll 8
            for (int e = 0; e < 128; e++)
                a2 += tbuf[e] * Wa_adj[e * 128 + t];
            g_B[n * 384 + 128 + t] = __float2half_rn(a2);
            red[t] = tv * ba_adj[t];
            __syncthreads();
#pragma unroll
            for (int s = 64; s > 0; s >>= 1) {
                if (t < s) red[t] += red[t + s];
                __syncthreads();
            }
            csum += red[0];
            __syncthreads();
        }

        {
            float tv = 0.f;
#pragma unroll 8
            for (int g = 0; g < 128; g++)
                tv += wcn[256 + g] * W_dis[g * 128 + t];
            tbuf[t] = tv;
            __syncthreads();
            float a2 = 0.f;
#pragma unroll 8
            for (int e = 0; e < 128; e++)
                a2 += tbuf[e] * Wa_dis[e * 128 + t];
            g_B[n * 384 + 256 + t] = __float2half_rn(a2);
            red[t] = tv * ba_dis[t];
            __syncthreads();
#pragma unroll
            for (int s = 64; s > 0; s >>= 1) {
                if (t < s) red[t] += red[t + s];
                __syncthreads();
            }
            csum += red[0];
        }

        if (t == 0) g_c[n] = csum + bWC[n] + bias[n];
        return;
    }

    // ---------------- gather + mean (float4 per lane) -----------------------
    const int u = blockIdx.x - FOLD_BLOCKS;
    const int lane = t & 31;
    const int w = t >> 5;

    __shared__ int sa[K_NEIGH];
    __shared__ int sd[K_NEIGH];
    __shared__ int sself;
    __shared__ float4 part[2][4][32];

    if (t < 32)       sa[t]      = adj[(size_t)u * K_NEIGH + t];
    else if (t < 64)  sd[t - 32] = dis[(size_t)u * K_NEIGH + (t - 32)];
    else if (t == 64) sself      = uid[u];
    __syncthreads();

    const float4* e4 = (const float4*)emb;   // 32 float4 per 128-dim row

    float4 vself;
    if (w == 2) vself = e4[(size_t)sself * 32 + lane];

    float4 aa = make_float4(0.f, 0.f, 0.f, 0.f);
    float4 ad = make_float4(0.f, 0.f, 0.f, 0.f);
#pragma unroll
    for (int j = 0; j < 8; j++) {
        const int k = w * 8 + j;
        float4 va = e4[(size_t)sa[k] * 32 + lane];
        float4 vd = e4[(size_t)sd[k] * 32 + lane];
        aa.x += va.x; aa.y += va.y; aa.z += va.z; aa.w += va.w;
        ad.x += vd.x; ad.y += vd.y; ad.z += vd.z; ad.w += vd.w;
    }
    part[0][w][lane] = aa;
    part[1][w][lane] = ad;

    if (w == 2) {
        uint2 pk;
        pk.x = pack_half2_u32(vself.x, vself.y);
        pk.y = pack_half2_u32(vself.z, vself.w);
        *(uint2*)&g_X[(size_t)u * 384 + lane * 4] = pk;
    }
    __syncthreads();

    if (t < 64) {
        const int which = t >> 5;       // 0=adj, 1=dis
        const int l = t & 31;
        float4 s0 = part[which][0][l];
        float4 s1 = part[which][1][l];
        float4 s2 = part[which][2][l];
        float4 s3 = part[which][3][l];
        const float sc = 1.0f / 32.0f;
        float x0 = (s0.x + s1.x + s2.x + s3.x) * sc;
        float x1 = (s0.y + s1.y + s2.y + s3.y) * sc;
        float x2 = (s0.z + s1.z + s2.z + s3.z) * sc;
        float x3 = (s0.w + s1.w + s2.w + s3.w) * sc;
        uint2 pk;
        pk.x = pack_half2_u32(x0, x1);
        pk.y = pack_half2_u32(x2, x3);
        *(uint2*)&g_X[(size_t)u * 384 + 128 + which * 128 + l * 4] = pk;
    }
}

// ---------------------------------------------------------------------------
// GEMM: Y = leaky( X[16384,384] @ A^T + c ) via fp16 mma.sync (R8-verbatim)
// K = 384, k-chunk 64, 6 iters. CTA 128x128, 8 warps (4m x 2n), warp 32x64.
// 3-stage cp.async pipeline, ONE __syncthreads per iter.
// ---------------------------------------------------------------------------
#define KCH      64
#define ROWB     144
#define STG_OP   (128 * ROWB)
#define STG_B    (2 * STG_OP)
#define NSTG     3
#define GSM_TOT  (NSTG * STG_B)          // 110592 B

__global__ __launch_bounds__(256, 2) void gemm_hmma_kernel() {
    extern __shared__ char gsm[];
    const uint32_t base = smem_u32(gsm);

    const int t = threadIdx.x;
    const int lane = t & 31;
    const int wid = t >> 5;
    const int wm = wid & 3;
    const int wn = wid >> 2;
    const int n0 = blockIdx.x * 128;
    const int m0 = blockIdx.y * 128;

    const uint32_t a_lm = (uint32_t)((lane & 15) * ROWB + (lane >> 4) * 16);
    const uint32_t b_lm = (uint32_t)(((lane & 7) + ((lane >> 4) << 3)) * ROWB
                                     + (((lane >> 3) & 1) << 4));

    float acc[2][8][4];
#pragma unroll
    for (int i = 0; i < 2; i++)
#pragma unroll
        for (int j = 0; j < 8; j++)
#pragma unroll
            for (int q = 0; q < 4; q++) acc[i][j][q] = 0.f;

    auto load_iter = [&](int it, int s) {
        const int kc = it * KCH;
        const uint32_t sb = base + (uint32_t)(s * STG_B);
#pragma unroll
        for (int j = 0; j < 4; j++) {
            const int q = t + j * 256;
            const int r = q >> 3;
            const int ch = q & 7;
            cp_async16(sb + (uint32_t)(r * ROWB + ch * 16),
                       g_X + (size_t)(m0 + r) * 384 + kc + ch * 8);
            cp_async16(sb + (uint32_t)(STG_OP + r * ROWB + ch * 16),
                       g_B + (size_t)(n0 + r) * 384 + kc + ch * 8);
        }
        cp_commit();
    };

    load_iter(0, 0);
    load_iter(1, 1);

    for (int it = 0; it < 6; it++) {
        if (it == 5) cp_wait<0>(); else cp_wait<1>();
        __syncthreads();

        const int s = it % NSTG;
        const uint32_t a_tile = base + (uint32_t)(s * STG_B + wm * 32 * ROWB) + a_lm;
        const uint32_t b_tile = base + (uint32_t)(s * STG_B + STG_OP + wn * 64 * ROWB) + b_lm;

#pragma unroll
        for (int ks = 0; ks < 4; ks++) {
            uint32_t af[2][4];
            uint32_t bf_[4][4];
#pragma unroll
            for (int mi = 0; mi < 2; mi++)
                ldsm_x4(af[mi][0], af[mi][1], af[mi][2], af[mi][3],
                        a_tile + (uint32_t)(mi * 16 * ROWB + ks * 32));
#pragma unroll
            for (int bj = 0; bj < 4; bj++)
                ldsm_x4(bf_[bj][0], bf_[bj][1], bf_[bj][2], bf_[bj][3],
                        b_tile + (uint32_t)(bj * 16 * ROWB + ks * 32));
#pragma unroll
            for (int mi = 0; mi < 2; mi++)
#pragma unroll
                for (int nj = 0; nj < 8; nj++)
                    mma16816(acc[mi][nj][0], acc[mi][nj][1],
                             acc[mi][nj][2], acc[mi][nj][3],
                             af[mi][0], af[mi][1], af[mi][2], af[mi][3],
                             bf_[nj >> 1][(nj & 1) * 2],
                             bf_[nj >> 1][(nj & 1) * 2 + 1]);
        }

        if (it + 2 < 6) load_iter(it + 2, (it + 2) % NSTG);
    }

    // ---- epilogue: += c, leaky relu, store to g_Y ----
    float cv[8][2];
#pragma unroll
    for (int nj = 0; nj < 8; nj++) {
        const int col = n0 + wn * 64 + nj * 8 + (lane & 3) * 2;
        cv[nj][0] = g_c[col];
        cv[nj][1] = g_c[col + 1];
    }
#pragma unroll
    for (int mi = 0; mi < 2; mi++) {
        const int row = m0 + wm * 32 + mi * 16 + (lane >> 2);
#pragma unroll
        for (int nj = 0; nj < 8; nj++) {
            const int col = n0 + wn * 64 + nj * 8 + (lane & 3) * 2;
            float y0 = acc[mi][nj][0] + cv[nj][0];
            float y1 = acc[mi][nj][1] + cv[nj][1];
            float y2 = acc[mi][nj][2] + cv[nj][0];
            float y3 = acc[mi][nj][3] + cv[nj][1];
            y0 = (y0 > 0.f) ? y0 : 0.2f * y0;
            y1 = (y1 > 0.f) ? y1 : 0.2f * y1;
            y2 = (y2 > 0.f) ? y2 : 0.2f * y2;
            y3 = (y3 > 0.f) ? y3 : 0.2f * y3;
            *(float2*)&g_Y[(size_t)row * 384 + col]       = make_float2(y0, y1);
            *(float2*)&g_Y[(size_t)(row + 8) * 384 + col] = make_float2(y2, y3);
        }
    }
}

// ---------------------------------------------------------------------------
// norm_gather v2: 2 rows per warp, interleaved loads (MLP=6 before reduce).
// out[b] = normalize(Y[nodes_idx[b]]). grid 2048 x 256 (16 rows per block).
// ---------------------------------------------------------------------------
__global__ void __launch_bounds__(256) norm_gather_kernel(
        const int* __restrict__ nodes_idx,
        float* __restrict__ out) {
    __shared__ int sidx[16];
    const int w = threadIdx.x >> 5;
    const int l = threadIdx.x & 31;
    if (threadIdx.x < 16) sidx[threadIdx.x] = nodes_idx[blockIdx.x * 16 + threadIdx.x];
    __syncthreads();

    const int b0 = blockIdx.x * 16 + w * 2;
    const int ua = sidx[w * 2];
    const int ub = sidx[w * 2 + 1];

    const float4* ya = (const float4*)(g_Y + (size_t)ua * 384);
    const float4* yb = (const float4*)(g_Y + (size_t)ub * 384);

    // 6 independent loads in flight
    float4 a0 = ya[l];
    float4 b0v = yb[l];
    float4 a1 = ya[l + 32];
    float4 b1v = yb[l + 32];
    float4 a2 = ya[l + 64];
    float4 b2v = yb[l + 64];

    float sa = a0.x * a0.x + a0.y * a0.y + a0.z * a0.z + a0.w * a0.w
             + a1.x * a1.x + a1.y * a1.y + a1.z * a1.z + a1.w * a1.w
             + a2.x * a2.x + a2.y * a2.y + a2.z * a2.z + a2.w * a2.w;
    float sb = b0v.x * b0v.x + b0v.y * b0v.y + b0v.z * b0v.z + b0v.w * b0v.w
             + b1v.x * b1v.x + b1v.y * b1v.y + b1v.z * b1v.z + b1v.w * b1v.w
             + b2v.x * b2v.x + b2v.y * b2v.y + b2v.z * b2v.z + b2v.w * b2v.w;

#pragma unroll
    for (int off = 16; off > 0; off >>= 1) {
        sa += __shfl_xor_sync(0xffffffffu, sa, off);
        sb += __shfl_xor_sync(0xffffffffu, sb, off);
    }

    const float inva = 1.0f / fmaxf(sqrtf(sa), 1e-12f);
    const float invb = 1.0f / fmaxf(sqrtf(sb), 1e-12f);

    float4* oa = (float4*)(out + (size_t)b0 * 384);
    float4* ob = (float4*)(out + (size_t)(b0 + 1) * 384);

    a0.x *= inva; a0.y *= inva; a0.z *= inva; a0.w *= inva;
    a1.x *= inva; a1.y *= inva; a1.z *= inva; a1.w *= inva;
    a2.x *= inva; a2.y *= inva; a2.z *= inva; a2.w *= inva;
    b0v.x *= invb; b0v.y *= invb; b0v.z *= invb; b0v.w *= invb;
    b1v.x *= invb; b1v.y *= invb; b1v.z *= invb; b1v.w *= invb;
    b2v.x *= invb; b2v.y *= invb; b2v.z *= invb; b2v.w *= invb;

    oa[l]      = a0;
    ob[l]      = b0v;
    oa[l + 32] = a1;
    ob[l + 32] = b1v;
    oa[l + 64] = a2;
    ob[l + 64] = b2v;
}

// ---------------------------------------------------------------------------
extern "C" void kernel_launch(void* const* d_in, const int* in_sizes, int n_in,
                              void* d_out, int out_size) {
    const float* emb    = (const float*)d_in[0];
    const float* Wa_adj = (const float*)d_in[1];
    const float* ba_adj = (const float*)d_in[2];
    const float* Wa_dis = (const float*)d_in[3];
    const float* ba_dis = (const float*)d_in[4];
    const float* W_self = (const float*)d_in[5];
    const float* W_adj  = (const float*)d_in[6];
    const float* W_dis  = (const float*)d_in[7];
    const float* WC     = (const float*)d_in[8];
    const float* bWC    = (const float*)d_in[9];
    const float* bias   = (const float*)d_in[10];
    const int* uid      = (const int*)d_in[11];
    const int* adj      = (const int*)d_in[12];
    const int* dis      = (const int*)d_in[13];
    const int* nidx     = (const int*)d_in[14];
    float* out          = (float*)d_out;

    cudaFuncSetAttribute(gemm_hmma_kernel,
                         cudaFuncAttributeMaxDynamicSharedMemorySize, GSM_TOT);

    fold_gather_kernel<<<FOLD_BLOCKS + U_NODES, 128>>>(
        emb, uid, adj, dis,
        Wa_adj, ba_adj, Wa_dis, ba_dis,
        W_self, W_adj, W_dis, WC, bWC, bias);
    gemm_hmma_kernel<<<dim3(3, 128), 256, GSM_TOT>>>();
    norm_gather_kernel<<<B_OUT / 16, 256>>>(nidx, out);
}

// round 16
// speedup vs baseline: 1.1508x; 1.1508x over previous
#include <cuda_runtime.h>
#include <cuda_bf16.h>
#include <cuda_fp16.h>
#include <cstdint>
#include <cstddef>

// ---------------------------------------------------------------------------
// SageLayer pipeline (R8 configuration — measured optimum, 124.5 us)
//   out[b] = normalize(leaky( X @ A^T + c ))[nodes_idx]
//   X[u] = [ emb[uid[u]] | mean_k emb[adj[u,k]] | mean_k emb[dis[u,k]] ]
//   Weights folded to one 384x384 fp16 matrix (one-pass per-row algebra:
//   WC2@(W@Wa) = (WC2@W)@Wa), folded inside the gather grid (blocks 0..383).
//   Gather: warp-per-8-rows LDG.128 + smem cross-warp reduce (DRAM ~71%).
//   GEMM: fp16 mma.sync, K=384, kch64, 3-stage cp.async, 8 warps 4m x 2n.
//
//   Measured dead-ends (do not revisit): phase fusion / co-residency with the
//   gather (R4/R9/R10), cp.async hoist + ssq precompute (R11), fp16 Y (R12),
//   512-thread GEMM (R13), 2-rows-per-warp norm (R14).
// ---------------------------------------------------------------------------

#define U_NODES 16384
#define K_NEIGH 32
#define D_IN    128
#define D_OUT   384
#define B_OUT   32768
#define FOLD_BLOCKS 384

// ---- device scratch ----
__device__ __align__(16) float g_c[384];
__device__ __align__(16) __half g_X[(size_t)U_NODES * 384];
__device__ __align__(16) __half g_B[384 * 384];            // folded A[n][k]
__device__ __align__(16) float g_Y[(size_t)U_NODES * 384];

// ---- helpers ----
__device__ __forceinline__ uint32_t smem_u32(const void* p) {
    uint32_t a;
    asm("{ .reg .u64 t; cvta.to.shared.u64 t, %1; cvt.u32.u64 %0, t; }"
        : "=r"(a) : "l"(p));
    return a;
}
__device__ __forceinline__ void cp_async16(uint32_t dst, const void* src) {
    asm volatile("cp.async.cg.shared.global [%0], [%1], 16;"
                 :: "r"(dst), "l"(src) : "memory");
}
__device__ __forceinline__ void cp_commit() {
    asm volatile("cp.async.commit_group;" ::: "memory");
}
template <int N>
__device__ __forceinline__ void cp_wait() {
    asm volatile("cp.async.wait_group %0;" :: "n"(N) : "memory");
}
__device__ __forceinline__ void ldsm_x4(uint32_t& r0, uint32_t& r1,
                                        uint32_t& r2, uint32_t& r3, uint32_t a) {
    asm volatile("ldmatrix.sync.aligned.m8n8.x4.shared.b16 {%0,%1,%2,%3}, [%4];"
                 : "=r"(r0), "=r"(r1), "=r"(r2), "=r"(r3) : "r"(a));
}
__device__ __forceinline__ void mma16816(float& c0, float& c1, float& c2, float& c3,
                                         uint32_t a0, uint32_t a1, uint32_t a2, uint32_t a3,
                                         uint32_t b0, uint32_t b1) {
    asm volatile(
        "mma.sync.aligned.m16n8k16.row.col.f32.f16.f16.f32 "
        "{%0,%1,%2,%3}, {%4,%5,%6,%7}, {%8,%9}, {%0,%1,%2,%3};"
        : "+f"(c0), "+f"(c1), "+f"(c2), "+f"(c3)
        : "r"(a0), "r"(a1), "r"(a2), "r"(a3), "r"(b0), "r"(b1));
}
__device__ __forceinline__ uint32_t pack_half2_u32(float a, float b) {
    __half2 h = __floats2half2_rn(a, b);
    return *(uint32_t*)&h;
}

// ---------------------------------------------------------------------------
// fused fold + gather kernel
//   blocks [0, 384):        fold output-row n of B and c
//   blocks [384, 384+16384): gather+mean node u = blockIdx.x - 384
//   128 threads per block.
// ---------------------------------------------------------------------------
__global__ void __launch_bounds__(128) fold_gather_kernel(
        const float* __restrict__ emb,
        const int* __restrict__ uid,
        const int* __restrict__ adj,
        const int* __restrict__ dis,
        const float* __restrict__ Wa_adj,
        const float* __restrict__ ba_adj,
        const float* __restrict__ Wa_dis,
        const float* __restrict__ ba_dis,
        const float* __restrict__ W_self,
        const float* __restrict__ W_adj,
        const float* __restrict__ W_dis,
        const float* __restrict__ WC,
        const float* __restrict__ bWC,
        const float* __restrict__ bias) {
    const int t = threadIdx.x;

    if (blockIdx.x < FOLD_BLOCKS) {
        // ---------------- fold: B[n][:] (fp16) and c[n] ---------------------
        const int n = blockIdx.x;
        __shared__ float wcn[384];
        __shared__ float tbuf[128];
        __shared__ float red[128];

        wcn[t]       = WC[n * 384 + t];
        wcn[t + 128] = WC[n * 384 + 128 + t];
        wcn[t + 256] = WC[n * 384 + 256 + t];
        __syncthreads();

        // self segment: B[n][k] = sum_e wcn[e] * W_self[e][k],  k = t
        {
            float a = 0.f;
#pragma unroll 8
            for (int e = 0; e < 128; e++)
                a += wcn[e] * W_self[e * 128 + t];
            g_B[n * 384 + t] = __float2half_rn(a);
        }

        float csum = 0.f;

        // adj segment: tv[e] = sum_g wcn[128+g] * W_adj[g][e]
        //              B[n][128+k] = sum_e tv[e] * Wa_adj[e][k]
        //              c += sum_e tv[e] * ba_adj[e]
        {
            float tv = 0.f;
#pragma unroll 8
            for (int g = 0; g < 128; g++)
                tv += wcn[128 + g] * W_adj[g * 128 + t];
            tbuf[t] = tv;
            __syncthreads();
            float a2 = 0.f;
#pragma unroll 8
            for (int e = 0; e < 128; e++)
                a2 += tbuf[e] * Wa_adj[e * 128 + t];
            g_B[n * 384 + 128 + t] = __float2half_rn(a2);
            red[t] = tv * ba_adj[t];
            __syncthreads();
#pragma unroll
            for (int s = 64; s > 0; s >>= 1) {
                if (t < s) red[t] += red[t + s];
                __syncthreads();
            }
            csum += red[0];
            __syncthreads();
        }

        // dis segment
        {
            float tv = 0.f;
#pragma unroll 8
            for (int g = 0; g < 128; g++)
                tv += wcn[256 + g] * W_dis[g * 128 + t];
            tbuf[t] = tv;
            __syncthreads();
            float a2 = 0.f;
#pragma unroll 8
            for (int e = 0; e < 128; e++)
                a2 += tbuf[e] * Wa_dis[e * 128 + t];
            g_B[n * 384 + 256 + t] = __float2half_rn(a2);
            red[t] = tv * ba_dis[t];
            __syncthreads();
#pragma unroll
            for (int s = 64; s > 0; s >>= 1) {
                if (t < s) red[t] += red[t + s];
                __syncthreads();
            }
            csum += red[0];
        }

        if (t == 0) g_c[n] = csum + bWC[n] + bias[n];
        return;
    }

    // ---------------- gather + mean (float4 per lane) -----------------------
    const int u = blockIdx.x - FOLD_BLOCKS;
    const int lane = t & 31;
    const int w = t >> 5;

    __shared__ int sa[K_NEIGH];
    __shared__ int sd[K_NEIGH];
    __shared__ int sself;
    __shared__ float4 part[2][4][32];

    if (t < 32)       sa[t]      = adj[(size_t)u * K_NEIGH + t];
    else if (t < 64)  sd[t - 32] = dis[(size_t)u * K_NEIGH + (t - 32)];
    else if (t == 64) sself      = uid[u];
    __syncthreads();

    const float4* e4 = (const float4*)emb;   // 32 float4 per 128-dim row

    // warp 2 also loads the self row (issued early, independent)
    float4 vself;
    if (w == 2) vself = e4[(size_t)sself * 32 + lane];

    float4 aa = make_float4(0.f, 0.f, 0.f, 0.f);
    float4 ad = make_float4(0.f, 0.f, 0.f, 0.f);
#pragma unroll
    for (int j = 0; j < 8; j++) {
        const int k = w * 8 + j;
        float4 va = e4[(size_t)sa[k] * 32 + lane];
        float4 vd = e4[(size_t)sd[k] * 32 + lane];
        aa.x += va.x; aa.y += va.y; aa.z += va.z; aa.w += va.w;
        ad.x += vd.x; ad.y += vd.y; ad.z += vd.z; ad.w += vd.w;
    }
    part[0][w][lane] = aa;
    part[1][w][lane] = ad;

    // self store (dims lane*4..lane*4+3) — independent of the reduce
    if (w == 2) {
        uint2 pk;
        pk.x = pack_half2_u32(vself.x, vself.y);
        pk.y = pack_half2_u32(vself.z, vself.w);
        *(uint2*)&g_X[(size_t)u * 384 + lane * 4] = pk;
    }
    __syncthreads();

    // reduce tasks: t in [0,32): adj dims l*4.., t in [32,64): dis
    if (t < 64) {
        const int which = t >> 5;       // 0=adj, 1=dis
        const int l = t & 31;
        float4 s0 = part[which][0][l];
        float4 s1 = part[which][1][l];
        float4 s2 = part[which][2][l];
        float4 s3 = part[which][3][l];
        const float sc = 1.0f / 32.0f;
        float x0 = (s0.x + s1.x + s2.x + s3.x) * sc;
        float x1 = (s0.y + s1.y + s2.y + s3.y) * sc;
        float x2 = (s0.z + s1.z + s2.z + s3.z) * sc;
        float x3 = (s0.w + s1.w + s2.w + s3.w) * sc;
        uint2 pk;
        pk.x = pack_half2_u32(x0, x1);
        pk.y = pack_half2_u32(x2, x3);
        *(uint2*)&g_X[(size_t)u * 384 + 128 + which * 128 + l * 4] = pk;
    }
}

// ---------------------------------------------------------------------------
// GEMM: Y = leaky( X[16384,384] @ A^T + c ) via fp16 mma.sync
// K = 384, k-chunk 64, 6 iters. CTA 128x128, 8 warps (4m x 2n), warp 32x64.
// 3-stage cp.async pipeline, ONE __syncthreads per iter.
// smem rows padded to 144 B (stride 36 words -> conflict-free ldmatrix).
// ---------------------------------------------------------------------------
#define KCH      64
#define ROWB     144
#define STG_OP   (128 * ROWB)           // 18432 B per operand per stage
#define STG_B    (2 * STG_OP)           // 36864 B per stage (A+B)
#define NSTG     3
#define GSM_TOT  (NSTG * STG_B)         // 110592 B

__global__ __launch_bounds__(256, 2) void gemm_hmma_kernel() {
    extern __shared__ char gsm[];
    const uint32_t base = smem_u32(gsm);

    const int t = threadIdx.x;
    const int lane = t & 31;
    const int wid = t >> 5;
    const int wm = wid & 3;
    const int wn = wid >> 2;
    const int n0 = blockIdx.x * 128;
    const int m0 = blockIdx.y * 128;

    const uint32_t a_lm = (uint32_t)((lane & 15) * ROWB + (lane >> 4) * 16);
    const uint32_t b_lm = (uint32_t)(((lane & 7) + ((lane >> 4) << 3)) * ROWB
                                     + (((lane >> 3) & 1) << 4));

    float acc[2][8][4];
#pragma unroll
    for (int i = 0; i < 2; i++)
#pragma unroll
        for (int j = 0; j < 8; j++)
#pragma unroll
            for (int q = 0; q < 4; q++) acc[i][j][q] = 0.f;

    auto load_iter = [&](int it, int s) {
        const int kc = it * KCH;
        const uint32_t sb = base + (uint32_t)(s * STG_B);
#pragma unroll
        for (int j = 0; j < 4; j++) {
            const int q = t + j * 256;
            const int r = q >> 3;
            const int ch = q & 7;
            cp_async16(sb + (uint32_t)(r * ROWB + ch * 16),
                       g_X + (size_t)(m0 + r) * 384 + kc + ch * 8);
            cp_async16(sb + (uint32_t)(STG_OP + r * ROWB + ch * 16),
                       g_B + (size_t)(n0 + r) * 384 + kc + ch * 8);
        }
        cp_commit();
    };

    load_iter(0, 0);
    load_iter(1, 1);

    for (int it = 0; it < 6; it++) {
        if (it == 5) cp_wait<0>(); else cp_wait<1>();
        __syncthreads();

        const int s = it % NSTG;
        const uint32_t a_tile = base + (uint32_t)(s * STG_B + wm * 32 * ROWB) + a_lm;
        const uint32_t b_tile = base + (uint32_t)(s * STG_B + STG_OP + wn * 64 * ROWB) + b_lm;

#pragma unroll
        for (int ks = 0; ks < 4; ks++) {
            uint32_t af[2][4];
            uint32_t bf_[4][4];
#pragma unroll
            for (int mi = 0; mi < 2; mi++)
                ldsm_x4(af[mi][0], af[mi][1], af[mi][2], af[mi][3],
                        a_tile + (uint32_t)(mi * 16 * ROWB + ks * 32));
#pragma unroll
            for (int bj = 0; bj < 4; bj++)
                ldsm_x4(bf_[bj][0], bf_[bj][1], bf_[bj][2], bf_[bj][3],
                        b_tile + (uint32_t)(bj * 16 * ROWB + ks * 32));
#pragma unroll
            for (int mi = 0; mi < 2; mi++)
#pragma unroll
                for (int nj = 0; nj < 8; nj++)
                    mma16816(acc[mi][nj][0], acc[mi][nj][1],
                             acc[mi][nj][2], acc[mi][nj][3],
                             af[mi][0], af[mi][1], af[mi][2], af[mi][3],
                             bf_[nj >> 1][(nj & 1) * 2],
                             bf_[nj >> 1][(nj & 1) * 2 + 1]);
        }

        if (it + 2 < 6) load_iter(it + 2, (it + 2) % NSTG);
    }

    // ---- epilogue: += c, leaky relu, store to g_Y ----
    float cv[8][2];
#pragma unroll
    for (int nj = 0; nj < 8; nj++) {
        const int col = n0 + wn * 64 + nj * 8 + (lane & 3) * 2;
        cv[nj][0] = g_c[col];
        cv[nj][1] = g_c[col + 1];
    }
#pragma unroll
    for (int mi = 0; mi < 2; mi++) {
        const int row = m0 + wm * 32 + mi * 16 + (lane >> 2);
#pragma unroll
        for (int nj = 0; nj < 8; nj++) {
            const int col = n0 + wn * 64 + nj * 8 + (lane & 3) * 2;
            float y0 = acc[mi][nj][0] + cv[nj][0];
            float y1 = acc[mi][nj][1] + cv[nj][1];
            float y2 = acc[mi][nj][2] + cv[nj][0];
            float y3 = acc[mi][nj][3] + cv[nj][1];
            y0 = (y0 > 0.f) ? y0 : 0.2f * y0;
            y1 = (y1 > 0.f) ? y1 : 0.2f * y1;
            y2 = (y2 > 0.f) ? y2 : 0.2f * y2;
            y3 = (y3 > 0.f) ? y3 : 0.2f * y3;
            *(float2*)&g_Y[(size_t)row * 384 + col]       = make_float2(y0, y1);
            *(float2*)&g_Y[(size_t)(row + 8) * 384 + col] = make_float2(y2, y3);
        }
    }
}

// ---------------------------------------------------------------------------
// norm_gather: out[b] = normalize(Y[nodes_idx[b]])  (one warp per row)
// ---------------------------------------------------------------------------
__global__ void norm_gather_kernel(const int* __restrict__ nodes_idx,
                                   float* __restrict__ out) {
    __shared__ int sidx[8];
    const int w = threadIdx.x >> 5;
    const int l = threadIdx.x & 31;
    if (threadIdx.x < 8) sidx[threadIdx.x] = nodes_idx[blockIdx.x * 8 + threadIdx.x];
    __syncthreads();

    const int b = blockIdx.x * 8 + w;
    const int u = sidx[w];

    const float4* yr = (const float4*)(g_Y + (size_t)u * 384);
    float4 v0 = yr[l];
    float4 v1 = yr[l + 32];
    float4 v2 = yr[l + 64];

    float s = v0.x * v0.x + v0.y * v0.y + v0.z * v0.z + v0.w * v0.w
            + v1.x * v1.x + v1.y * v1.y + v1.z * v1.z + v1.w * v1.w
            + v2.x * v2.x + v2.y * v2.y + v2.z * v2.z + v2.w * v2.w;
#pragma unroll
    for (int off = 16; off > 0; off >>= 1)
        s += __shfl_xor_sync(0xffffffffu, s, off);

    const float inv = 1.0f / fmaxf(sqrtf(s), 1e-12f);

    float4* o = (float4*)(out + (size_t)b * 384);
    v0.x *= inv; v0.y *= inv; v0.z *= inv; v0.w *= inv;
    v1.x *= inv; v1.y *= inv; v1.z *= inv; v1.w *= inv;
    v2.x *= inv; v2.y *= inv; v2.z *= inv; v2.w *= inv;
    o[l]      = v0;
    o[l + 32] = v1;
    o[l + 64] = v2;
}

// ---------------------------------------------------------------------------
extern "C" void kernel_launch(void* const* d_in, const int* in_sizes, int n_in,
                              void* d_out, int out_size) {
    const float* emb    = (const float*)d_in[0];
    const float* Wa_adj = (const float*)d_in[1];
    const float* ba_adj = (const float*)d_in[2];
    const float* Wa_dis = (const float*)d_in[3];
    const float* ba_dis = (const float*)d_in[4];
    const float* W_self = (const float*)d_in[5];
    const float* W_adj  = (const float*)d_in[6];
    const float* W_dis  = (const float*)d_in[7];
    const float* WC     = (const float*)d_in[8];
    const float* bWC    = (const float*)d_in[9];
    const float* bias   = (const float*)d_in[10];
    const int* uid      = (const int*)d_in[11];
    const int* adj      = (const int*)d_in[12];
    const int* dis      = (const int*)d_in[13];
    const int* nidx     = (const int*)d_in[14];
    float* out          = (float*)d_out;

    cudaFuncSetAttribute(gemm_hmma_kernel,
                         cudaFuncAttributeMaxDynamicSharedMemorySize, GSM_TOT);

    fold_gather_kernel<<<FOLD_BLOCKS + U_NODES, 128>>>(
        emb, uid, adj, dis,
        Wa_adj, ba_adj, Wa_dis, ba_dis,
        W_self, W_adj, W_dis, WC, bWC, bias);
    gemm_hmma_kernel<<<dim3(3, 128), 256, GSM_TOT>>>();
    norm_gather_kernel<<<B_OUT / 8, 256>>>(nidx, out);
}

// round 17
// speedup vs baseline: 1.1540x; 1.0028x over previous
#include <cuda_runtime.h>
#include <cuda_bf16.h>
#include <cuda_fp16.h>
#include <cstdint>
#include <cstddef>

// ---------------------------------------------------------------------------
// SageLayer pipeline v16: R8 config (measured 124.5us) with a persistent-CTA
// GEMM (grid = 296 = 2 CTAs x 148 SMs; each CTA loops over tiles bi, bi+296)
// to remove the 1.3-wave quantization tail. Mainloop/epilogue unchanged.
//   out[b] = normalize(leaky( X @ A^T + c ))[nodes_idx]
//   X[u] = [ emb[uid[u]] | mean_k emb[adj[u,k]] | mean_k emb[dis[u,k]] ]
//   Weights folded to one 384x384 fp16 matrix inside the gather grid.
//
//   Measured dead-ends (do not revisit): phase fusion / co-residency with the
//   gather (R4/R9/R10), cp.async hoist + ssq precompute (R11), fp16 Y (R12),
//   512-thread GEMM (R13), 2-rows-per-warp norm (R14).
// ---------------------------------------------------------------------------

#define U_NODES 16384
#define K_NEIGH 32
#define D_IN    128
#define D_OUT   384
#define B_OUT   32768
#define FOLD_BLOCKS 384

#define GEMM_TILES 384           // 3 n-tiles x 128 m-tiles
#define GEMM_CTAS  296           // 2 per SM x 148 SMs

// ---- device scratch ----
__device__ __align__(16) float g_c[384];
__device__ __align__(16) __half g_X[(size_t)U_NODES * 384];
__device__ __align__(16) __half g_B[384 * 384];            // folded A[n][k]
__device__ __align__(16) float g_Y[(size_t)U_NODES * 384];

// ---- helpers ----
__device__ __forceinline__ uint32_t smem_u32(const void* p) {
    uint32_t a;
    asm("{ .reg .u64 t; cvta.to.shared.u64 t, %1; cvt.u32.u64 %0, t; }"
        : "=r"(a) : "l"(p));
    return a;
}
__device__ __forceinline__ void cp_async16(uint32_t dst, const void* src) {
    asm volatile("cp.async.cg.shared.global [%0], [%1], 16;"
                 :: "r"(dst), "l"(src) : "memory");
}
__device__ __forceinline__ void cp_commit() {
    asm volatile("cp.async.commit_group;" ::: "memory");
}
template <int N>
__device__ __forceinline__ void cp_wait() {
    asm volatile("cp.async.wait_group %0;" :: "n"(N) : "memory");
}
__device__ __forceinline__ void ldsm_x4(uint32_t& r0, uint32_t& r1,
                                        uint32_t& r2, uint32_t& r3, uint32_t a) {
    asm volatile("ldmatrix.sync.aligned.m8n8.x4.shared.b16 {%0,%1,%2,%3}, [%4];"
                 : "=r"(r0), "=r"(r1), "=r"(r2), "=r"(r3) : "r"(a));
}
__device__ __forceinline__ void mma16816(float& c0, float& c1, float& c2, float& c3,
                                         uint32_t a0, uint32_t a1, uint32_t a2, uint32_t a3,
                                         uint32_t b0, uint32_t b1) {
    asm volatile(
        "mma.sync.aligned.m16n8k16.row.col.f32.f16.f16.f32 "
        "{%0,%1,%2,%3}, {%4,%5,%6,%7}, {%8,%9}, {%0,%1,%2,%3};"
        : "+f"(c0), "+f"(c1), "+f"(c2), "+f"(c3)
        : "r"(a0), "r"(a1), "r"(a2), "r"(a3), "r"(b0), "r"(b1));
}
__device__ __forceinline__ uint32_t pack_half2_u32(float a, float b) {
    __half2 h = __floats2half2_rn(a, b);
    return *(uint32_t*)&h;
}

// ---------------------------------------------------------------------------
// fused fold + gather kernel (R8-verbatim)
// ---------------------------------------------------------------------------
__global__ void __launch_bounds__(128) fold_gather_kernel(
        const float* __restrict__ emb,
        const int* __restrict__ uid,
        const int* __restrict__ adj,
        const int* __restrict__ dis,
        const float* __restrict__ Wa_adj,
        const float* __restrict__ ba_adj,
        const float* __restrict__ Wa_dis,
        const float* __restrict__ ba_dis,
        const float* __restrict__ W_self,
        const float* __restrict__ W_adj,
        const float* __restrict__ W_dis,
        const float* __restrict__ WC,
        const float* __restrict__ bWC,
        const float* __restrict__ bias) {
    const int t = threadIdx.x;

    if (blockIdx.x < FOLD_BLOCKS) {
        const int n = blockIdx.x;
        __shared__ float wcn[384];
        __shared__ float tbuf[128];
        __shared__ float red[128];

        wcn[t]       = WC[n * 384 + t];
        wcn[t + 128] = WC[n * 384 + 128 + t];
        wcn[t + 256] = WC[n * 384 + 256 + t];
        __syncthreads();

        {
            float a = 0.f;
#pragma unroll 8
            for (int e = 0; e < 128; e++)
                a += wcn[e] * W_self[e * 128 + t];
            g_B[n * 384 + t] = __float2half_rn(a);
        }

        float csum = 0.f;

        {
            float tv = 0.f;
#pragma unroll 8
            for (int g = 0; g < 128; g++)
                tv += wcn[128 + g] * W_adj[g * 128 + t];
            tbuf[t] = tv;
            __syncthreads();
            float a2 = 0.f;
#pragma unroll 8
            for (int e = 0; e < 128; e++)
                a2 += tbuf[e] * Wa_adj[e * 128 + t];
            g_B[n * 384 + 128 + t] = __float2half_rn(a2);
            red[t] = tv * ba_adj[t];
            __syncthreads();
#pragma unroll
            for (int s = 64; s > 0; s >>= 1) {
                if (t < s) red[t] += red[t + s];
                __syncthreads();
            }
            csum += red[0];
            __syncthreads();
        }

        {
            float tv = 0.f;
#pragma unroll 8
            for (int g = 0; g < 128; g++)
                tv += wcn[256 + g] * W_dis[g * 128 + t];
            tbuf[t] = tv;
            __syncthreads();
            float a2 = 0.f;
#pragma unroll 8
            for (int e = 0; e < 128; e++)
                a2 += tbuf[e] * Wa_dis[e * 128 + t];
            g_B[n * 384 + 256 + t] = __float2half_rn(a2);
            red[t] = tv * ba_dis[t];
            __syncthreads();
#pragma unroll
            for (int s = 64; s > 0; s >>= 1) {
                if (t < s) red[t] += red[t + s];
                __syncthreads();
            }
            csum += red[0];
        }

        if (t == 0) g_c[n] = csum + bWC[n] + bias[n];
        return;
    }

    // ---------------- gather + mean (float4 per lane) -----------------------
    const int u = blockIdx.x - FOLD_BLOCKS;
    const int lane = t & 31;
    const int w = t >> 5;

    __shared__ int sa[K_NEIGH];
    __shared__ int sd[K_NEIGH];
    __shared__ int sself;
    __shared__ float4 part[2][4][32];

    if (t < 32)       sa[t]      = adj[(size_t)u * K_NEIGH + t];
    else if (t < 64)  sd[t - 32] = dis[(size_t)u * K_NEIGH + (t - 32)];
    else if (t == 64) sself      = uid[u];
    __syncthreads();

    const float4* e4 = (const float4*)emb;

    float4 vself;
    if (w == 2) vself = e4[(size_t)sself * 32 + lane];

    float4 aa = make_float4(0.f, 0.f, 0.f, 0.f);
    float4 ad = make_float4(0.f, 0.f, 0.f, 0.f);
#pragma unroll
    for (int j = 0; j < 8; j++) {
        const int k = w * 8 + j;
        float4 va = e4[(size_t)sa[k] * 32 + lane];
        float4 vd = e4[(size_t)sd[k] * 32 + lane];
        aa.x += va.x; aa.y += va.y; aa.z += va.z; aa.w += va.w;
        ad.x += vd.x; ad.y += vd.y; ad.z += vd.z; ad.w += vd.w;
    }
    part[0][w][lane] = aa;
    part[1][w][lane] = ad;

    if (w == 2) {
        uint2 pk;
        pk.x = pack_half2_u32(vself.x, vself.y);
        pk.y = pack_half2_u32(vself.z, vself.w);
        *(uint2*)&g_X[(size_t)u * 384 + lane * 4] = pk;
    }
    __syncthreads();

    if (t < 64) {
        const int which = t >> 5;
        const int l = t & 31;
        float4 s0 = part[which][0][l];
        float4 s1 = part[which][1][l];
        float4 s2 = part[which][2][l];
        float4 s3 = part[which][3][l];
        const float sc = 1.0f / 32.0f;
        float x0 = (s0.x + s1.x + s2.x + s3.x) * sc;
        float x1 = (s0.y + s1.y + s2.y + s3.y) * sc;
        float x2 = (s0.z + s1.z + s2.z + s3.z) * sc;
        float x3 = (s0.w + s1.w + s2.w + s3.w) * sc;
        uint2 pk;
        pk.x = pack_half2_u32(x0, x1);
        pk.y = pack_half2_u32(x2, x3);
        *(uint2*)&g_X[(size_t)u * 384 + 128 + which * 128 + l * 4] = pk;
    }
}

// ---------------------------------------------------------------------------
// GEMM (persistent): Y = leaky( X @ A^T + c ) via fp16 mma.sync
// 296 CTAs; CTA bi processes tiles {bi, bi+296} (second only if < 384).
// Per tile: CTA 128x128, 8 warps 4m x 2n, K=384 kch64, 3-stage cp.async.
// ---------------------------------------------------------------------------
#define KCH      64
#define ROWB     144
#define STG_OP   (128 * ROWB)
#define STG_B    (2 * STG_OP)
#define NSTG     3
#define GSM_TOT  (NSTG * STG_B)          // 110592 B

__global__ __launch_bounds__(256, 2) void gemm_hmma_kernel() {
    extern __shared__ char gsm[];
    const uint32_t base = smem_u32(gsm);

    const int t = threadIdx.x;
    const int lane = t & 31;
    const int wid = t >> 5;
    const int wm = wid & 3;
    const int wn = wid >> 2;

    const uint32_t a_lm = (uint32_t)((lane & 15) * ROWB + (lane >> 4) * 16);
    const uint32_t b_lm = (uint32_t)(((lane & 7) + ((lane >> 4) << 3)) * ROWB
                                     + (((lane >> 3) & 1) << 4));

    for (int tile = blockIdx.x; tile < GEMM_TILES; tile += GEMM_CTAS) {
        const int nb = tile % 3;
        const int mb = tile / 3;
        const int n0 = nb * 128;
        const int m0 = mb * 128;

        float acc[2][8][4];
#pragma unroll
        for (int i = 0; i < 2; i++)
#pragma unroll
            for (int j = 0; j < 8; j++)
#pragma unroll
                for (int q = 0; q < 4; q++) acc[i][j][q] = 0.f;

        auto load_iter = [&](int it, int s) {
            const int kc = it * KCH;
            const uint32_t sb = base + (uint32_t)(s * STG_B);
#pragma unroll
            for (int j = 0; j < 4; j++) {
                const int q = t + j * 256;
                const int r = q >> 3;
                const int ch = q & 7;
                cp_async16(sb + (uint32_t)(r * ROWB + ch * 16),
                           g_X + (size_t)(m0 + r) * 384 + kc + ch * 8);
                cp_async16(sb + (uint32_t)(STG_OP + r * ROWB + ch * 16),
                           g_B + (size_t)(n0 + r) * 384 + kc + ch * 8);
            }
            cp_commit();
        };

        load_iter(0, 0);
        load_iter(1, 1);

        for (int it = 0; it < 6; it++) {
            if (it == 5) cp_wait<0>(); else cp_wait<1>();
            __syncthreads();

            const int s = it % NSTG;
            const uint32_t a_tile = base + (uint32_t)(s * STG_B + wm * 32 * ROWB) + a_lm;
            const uint32_t b_tile = base + (uint32_t)(s * STG_B + STG_OP + wn * 64 * ROWB) + b_lm;

#pragma unroll
            for (int ks = 0; ks < 4; ks++) {
                uint32_t af[2][4];
                uint32_t bf_[4][4];
#pragma unroll
                for (int mi = 0; mi < 2; mi++)
                    ldsm_x4(af[mi][0], af[mi][1], af[mi][2], af[mi][3],
                            a_tile + (uint32_t)(mi * 16 * ROWB + ks * 32));
#pragma unroll
                for (int bj = 0; bj < 4; bj++)
                    ldsm_x4(bf_[bj][0], bf_[bj][1], bf_[bj][2], bf_[bj][3],
                            b_tile + (uint32_t)(bj * 16 * ROWB + ks * 32));
#pragma unroll
                for (int mi = 0; mi < 2; mi++)
#pragma unroll
                    for (int nj = 0; nj < 8; nj++)
                        mma16816(acc[mi][nj][0], acc[mi][nj][1],
                                 acc[mi][nj][2], acc[mi][nj][3],
                                 af[mi][0], af[mi][1], af[mi][2], af[mi][3],
                                 bf_[nj >> 1][(nj & 1) * 2],
                                 bf_[nj >> 1][(nj & 1) * 2 + 1]);
            }

            if (it + 2 < 6) load_iter(it + 2, (it + 2) % NSTG);
        }

        // ---- epilogue: += c, leaky relu, store to g_Y ----
        float cv[8][2];
#pragma unroll
        for (int nj = 0; nj < 8; nj++) {
            const int col = n0 + wn * 64 + nj * 8 + (lane & 3) * 2;
            cv[nj][0] = g_c[col];
            cv[nj][1] = g_c[col + 1];
        }
#pragma unroll
        for (int mi = 0; mi < 2; mi++) {
            const int row = m0 + wm * 32 + mi * 16 + (lane >> 2);
#pragma unroll
            for (int nj = 0; nj < 8; nj++) {
                const int col = n0 + wn * 64 + nj * 8 + (lane & 3) * 2;
                float y0 = acc[mi][nj][0] + cv[nj][0];
                float y1 = acc[mi][nj][1] + cv[nj][1];
                float y2 = acc[mi][nj][2] + cv[nj][0];
                float y3 = acc[mi][nj][3] + cv[nj][1];
                y0 = (y0 > 0.f) ? y0 : 0.2f * y0;
                y1 = (y1 > 0.f) ? y1 : 0.2f * y1;
                y2 = (y2 > 0.f) ? y2 : 0.2f * y2;
                y3 = (y3 > 0.f) ? y3 : 0.2f * y3;
                *(float2*)&g_Y[(size_t)row * 384 + col]       = make_float2(y0, y1);
                *(float2*)&g_Y[(size_t)(row + 8) * 384 + col] = make_float2(y2, y3);
            }
        }

        // smem stages are re-filled from scratch next tile; all reads done.
        __syncthreads();
    }
}

// ---------------------------------------------------------------------------
// norm_gather: out[b] = normalize(Y[nodes_idx[b]])  (R8-verbatim)
// ---------------------------------------------------------------------------
__global__ void norm_gather_kernel(const int* __restrict__ nodes_idx,
                                   float* __restrict__ out) {
    __shared__ int sidx[8];
    const int w = threadIdx.x >> 5;
    const int l = threadIdx.x & 31;
    if (threadIdx.x < 8) sidx[threadIdx.x] = nodes_idx[blockIdx.x * 8 + threadIdx.x];
    __syncthreads();

    const int b = blockIdx.x * 8 + w;
    const int u = sidx[w];

    const float4* yr = (const float4*)(g_Y + (size_t)u * 384);
    float4 v0 = yr[l];
    float4 v1 = yr[l + 32];
    float4 v2 = yr[l + 64];

    float s = v0.x * v0.x + v0.y * v0.y + v0.z * v0.z + v0.w * v0.w
            + v1.x * v1.x + v1.y * v1.y + v1.z * v1.z + v1.w * v1.w
            + v2.x * v2.x + v2.y * v2.y + v2.z * v2.z + v2.w * v2.w;
#pragma unroll
    for (int off = 16; off > 0; off >>= 1)
        s += __shfl_xor_sync(0xffffffffu, s, off);

    const float inv = 1.0f / fmaxf(sqrtf(s), 1e-12f);

    float4* o = (float4*)(out + (size_t)b * 384);
    v0.x *= inv; v0.y *= inv; v0.z *= inv; v0.w *= inv;
    v1.x *= inv; v1.y *= inv; v1.z *= inv; v1.w *= inv;
    v2.x *= inv; v2.y *= inv; v2.z *= inv; v2.w *= inv;
    o[l]      = v0;
    o[l + 32] = v1;
    o[l + 64] = v2;
}

// ---------------------------------------------------------------------------
extern "C" void kernel_launch(void* const* d_in, const int* in_sizes, int n_in,
                              void* d_out, int out_size) {
    const float* emb    = (const float*)d_in[0];
    const float* Wa_adj = (const float*)d_in[1];
    const float* ba_adj = (const float*)d_in[2];
    const float* Wa_dis = (const float*)d_in[3];
    const float* ba_dis = (const float*)d_in[4];
    const float* W_self = (const float*)d_in[5];
    const float* W_adj  = (const float*)d_in[6];
    const float* W_dis  = (const float*)d_in[7];
    const float* WC     = (const float*)d_in[8];
    const float* bWC    = (const float*)d_in[9];
    const float* bias   = (const float*)d_in[10];
    const int* uid      = (const int*)d_in[11];
    const int* adj      = (const int*)d_in[12];
    const int* dis      = (const int*)d_in[13];
    const int* nidx     = (const int*)d_in[14];
    float* out          = (float*)d_out;

    cudaFuncSetAttribute(gemm_hmma_kernel,
                         cudaFuncAttributeMaxDynamicSharedMemorySize, GSM_TOT);

    fold_gather_kernel<<<FOLD_BLOCKS + U_NODES, 128>>>(
        emb, uid, adj, dis,
        Wa_adj, ba_adj, Wa_dis, ba_dis,
        W_self, W_adj, W_dis, WC, bWC, bias);
    gemm_hmma_kernel<<<GEMM_CTAS, 256, GSM_TOT>>>();
    norm_gather_kernel<<<B_OUT / 8, 256>>>(nidx, out);
}